// round 2
// baseline (speedup 1.0000x reference)
#include <cuda_runtime.h>
#include <cuda_bf16.h>
#include <cstdint>

// Histogram_15126874816754:
//   out[b, (p>0), y, x] += |p|/STD  over N events, then clip at 1.0.
// Inputs: x:int32[N], y:int32[N], p:f32[N], b:int32[N], width, height, batch.
// Output: f32[B*2*H*W]  (14.75M elements -> 32-bit index is safe)

#define INV_STD_C  (1.0f / 20.0f)
#define CLIP_MAX_C 1.0f

// ---------------------------------------------------------------------------
// Scatter: 8 events/thread, front-batched 128-bit loads (MLP=8),
// 32-bit flattened index, RED.E.ADD.F32 (atomicAdd result discarded).
// ---------------------------------------------------------------------------
__global__ void __launch_bounds__(256)
hist_scatter_kernel(const int4* __restrict__ xs,
                    const int4* __restrict__ ys,
                    const float4* __restrict__ ps,
                    const int4* __restrict__ bs,
                    const int* __restrict__ wp,
                    const int* __restrict__ hp,
                    float* __restrict__ out,
                    int n8)   // number of 8-event groups
{
    const int W = __ldg(wp);
    const int H = __ldg(hp);

    const int i = blockIdx.x * blockDim.x + threadIdx.x;
    if (i >= n8) return;

    // Front-batch all 8 loads per array (ptxas hoists these -> MLP ~8)
    const int4   x0 = __ldg(xs + 2 * i),     x1 = __ldg(xs + 2 * i + 1);
    const int4   y0 = __ldg(ys + 2 * i),     y1 = __ldg(ys + 2 * i + 1);
    const float4 p0 = __ldg(ps + 2 * i),     p1 = __ldg(ps + 2 * i + 1);
    const int4   b0 = __ldg(bs + 2 * i),     b1 = __ldg(bs + 2 * i + 1);

#define SCATTER_ONE(xx, yy, pp, bb)                                        \
    {                                                                      \
        const int pos = (pp) > 0.0f;                                       \
        const int idx = (((bb) * 2 + pos) * H + (yy)) * W + (xx);          \
        atomicAdd(out + idx, fabsf(pp) * INV_STD_C);                       \
    }

    SCATTER_ONE(x0.x, y0.x, p0.x, b0.x)
    SCATTER_ONE(x0.y, y0.y, p0.y, b0.y)
    SCATTER_ONE(x0.z, y0.z, p0.z, b0.z)
    SCATTER_ONE(x0.w, y0.w, p0.w, b0.w)
    SCATTER_ONE(x1.x, y1.x, p1.x, b1.x)
    SCATTER_ONE(x1.y, y1.y, p1.y, b1.y)
    SCATTER_ONE(x1.z, y1.z, p1.z, b1.z)
    SCATTER_ONE(x1.w, y1.w, p1.w, b1.w)
#undef SCATTER_ONE
}

// Scalar tail for n % 8 events (no-op for N = 8M).
__global__ void
hist_scatter_tail_kernel(const int* __restrict__ xs,
                         const int* __restrict__ ys,
                         const float* __restrict__ ps,
                         const int* __restrict__ bs,
                         const int* __restrict__ wp,
                         const int* __restrict__ hp,
                         float* __restrict__ out,
                         int start, int n)
{
    const int k = start + blockIdx.x * blockDim.x + threadIdx.x;
    if (k >= n) return;
    const int W = __ldg(wp);
    const int H = __ldg(hp);
    const float pk = ps[k];
    const int pos = pk > 0.0f;
    const int idx = ((bs[k] * 2 + pos) * H + ys[k]) * W + xs[k];
    atomicAdd(out + idx, fabsf(pk) * INV_STD_C);
}

// ---------------------------------------------------------------------------
// Clip: read float4; store ONLY if some component exceeds 1.0 (rare).
// Untouched values are already correct (memset-0 or sum < 1), and their
// lines are dirty anyway, so skipping the store halves the L2 write stream.
// ---------------------------------------------------------------------------
__global__ void __launch_bounds__(256)
hist_clip_kernel(float* __restrict__ out, int n)
{
    const int n4 = n >> 2;
    const int i = blockIdx.x * blockDim.x + threadIdx.x;

    if (i < n4) {
        float4* o4 = reinterpret_cast<float4*>(out);
        float4 v = o4[i];
        if (v.x > CLIP_MAX_C || v.y > CLIP_MAX_C ||
            v.z > CLIP_MAX_C || v.w > CLIP_MAX_C) {
            v.x = fminf(v.x, CLIP_MAX_C);
            v.y = fminf(v.y, CLIP_MAX_C);
            v.z = fminf(v.z, CLIP_MAX_C);
            v.w = fminf(v.w, CLIP_MAX_C);
            o4[i] = v;
        }
    } else if (i == n4) {
        for (int k = n4 * 4; k < n; ++k) {
            const float v = out[k];
            if (v > CLIP_MAX_C) out[k] = CLIP_MAX_C;
        }
    }
}

// ---------------------------------------------------------------------------
extern "C" void kernel_launch(void* const* d_in, const int* in_sizes, int n_in,
                              void* d_out, int out_size)
{
    const int*   xs = (const int*)  d_in[0];
    const int*   ys = (const int*)  d_in[1];
    const float* ps = (const float*)d_in[2];
    const int*   bs = (const int*)  d_in[3];
    const int*   wp = (const int*)  d_in[4];
    const int*   hp = (const int*)  d_in[5];

    float* out = (float*)d_out;
    const int n = in_sizes[0];

    // 1) zero accumulation image (DMA fill, graph-capturable)
    cudaMemsetAsync(d_out, 0, (size_t)out_size * sizeof(float), 0);

    // 2) scatter-add: 8 events/thread
    {
        const int n8 = n >> 3;
        if (n8 > 0) {
            const int blocks = (n8 + 255) / 256;
            hist_scatter_kernel<<<blocks, 256>>>(
                (const int4*)xs, (const int4*)ys, (const float4*)ps,
                (const int4*)bs, wp, hp, out, n8);
        }
        const int tail = n & 7;
        if (tail) {
            hist_scatter_tail_kernel<<<1, 32>>>(xs, ys, ps, bs, wp, hp,
                                                out, n & ~7, n);
        }
    }

    // 3) clip (conditional store)
    {
        const int n4 = out_size >> 2;
        const int total_threads = n4 + ((out_size & 3) ? 1 : 0);
        const int blocks = (total_threads + 255) / 256;
        hist_clip_kernel<<<blocks, 256>>>(out, out_size);
    }
}

// round 3
// speedup vs baseline: 1.1092x; 1.1092x over previous
#include <cuda_runtime.h>
#include <cuda_bf16.h>
#include <cstdint>

// Histogram_15126874816754:
//   out[b, (p>0), y, x] += |p|/STD  over N events, then clip at 1.0.
// Inputs: x:int32[N], y:int32[N], p:f32[N], b:int32[N], width, height, batch.
// Output: f32[B*2*H*W] = 14.75M floats (59 MB -> fits L2; keep it resident).

#define INV_STD_C  (1.0f / 20.0f)
#define CLIP_MAX_C 1.0f

// L2 evict_last policy handle (per-thread, cheap uniform op)
__device__ __forceinline__ uint64_t make_evict_last_policy() {
    uint64_t pol;
    asm("createpolicy.fractional.L2::evict_last.b64 %0, 1.0;" : "=l"(pol));
    return pol;
}

// Fire-and-forget float atomic add with L2 evict_last hint (keeps image resident)
__device__ __forceinline__ void red_add_f32_evict_last(float* p, float v, uint64_t pol) {
    asm volatile(
        "red.relaxed.gpu.global.L2::cache_hint.add.f32 [%0], %1, %2;"
        :: "l"(p), "f"(v), "l"(pol) : "memory");
}

// ---------------------------------------------------------------------------
// Zero pass: store-based (not DMA memset) so the image lands in L2 with
// evict_last priority BEFORE the scatter -> no DRAM sector reads on first
// atomic touch, and the clip pass afterwards hits L2.
// ---------------------------------------------------------------------------
__global__ void __launch_bounds__(256)
hist_zero_kernel(float* __restrict__ out, int n)
{
    const int n4 = n >> 2;
    const int i = blockIdx.x * blockDim.x + threadIdx.x;
    const uint64_t pol = make_evict_last_policy();

    if (i < n4) {
        float4* o4 = reinterpret_cast<float4*>(out);
        const float z = 0.0f;
        asm volatile(
            "st.global.L2::cache_hint.v4.f32 [%0], {%1, %1, %1, %1}, %2;"
            :: "l"(o4 + i), "f"(z), "l"(pol) : "memory");
    } else if (i == n4) {
        for (int k = n4 * 4; k < n; ++k) out[k] = 0.0f;
    }
}

// ---------------------------------------------------------------------------
// Scatter: 8 events/thread. Inputs via __ldcs (evict-first streaming) so the
// 128 MB event stream does not thrash the L2-resident image. Atomics carry
// the evict_last hint.
// ---------------------------------------------------------------------------
__global__ void __launch_bounds__(256)
hist_scatter_kernel(const int4* __restrict__ xs,
                    const int4* __restrict__ ys,
                    const float4* __restrict__ ps,
                    const int4* __restrict__ bs,
                    const int* __restrict__ wp,
                    const int* __restrict__ hp,
                    float* __restrict__ out,
                    int n8)   // number of 8-event groups
{
    const int W = __ldg(wp);
    const int H = __ldg(hp);
    const uint64_t pol = make_evict_last_policy();

    const int i = blockIdx.x * blockDim.x + threadIdx.x;
    if (i >= n8) return;

    // Front-batched streaming loads (MLP ~8, evict-first in L2)
    const int4   x0 = __ldcs(xs + 2 * i),  x1 = __ldcs(xs + 2 * i + 1);
    const int4   y0 = __ldcs(ys + 2 * i),  y1 = __ldcs(ys + 2 * i + 1);
    const float4 p0 = __ldcs(ps + 2 * i),  p1 = __ldcs(ps + 2 * i + 1);
    const int4   b0 = __ldcs(bs + 2 * i),  b1 = __ldcs(bs + 2 * i + 1);

#define SCATTER_ONE(xx, yy, pp, bb)                                        \
    {                                                                      \
        const int pos = (pp) > 0.0f;                                       \
        const int idx = (((bb) * 2 + pos) * H + (yy)) * W + (xx);          \
        red_add_f32_evict_last(out + idx, fabsf(pp) * INV_STD_C, pol);     \
    }

    SCATTER_ONE(x0.x, y0.x, p0.x, b0.x)
    SCATTER_ONE(x0.y, y0.y, p0.y, b0.y)
    SCATTER_ONE(x0.z, y0.z, p0.z, b0.z)
    SCATTER_ONE(x0.w, y0.w, p0.w, b0.w)
    SCATTER_ONE(x1.x, y1.x, p1.x, b1.x)
    SCATTER_ONE(x1.y, y1.y, p1.y, b1.y)
    SCATTER_ONE(x1.z, y1.z, p1.z, b1.z)
    SCATTER_ONE(x1.w, y1.w, p1.w, b1.w)
#undef SCATTER_ONE
}

// Scalar tail for n % 8 events (no-op for N = 8M).
__global__ void
hist_scatter_tail_kernel(const int* __restrict__ xs,
                         const int* __restrict__ ys,
                         const float* __restrict__ ps,
                         const int* __restrict__ bs,
                         const int* __restrict__ wp,
                         const int* __restrict__ hp,
                         float* __restrict__ out,
                         int start, int n)
{
    const int k = start + blockIdx.x * blockDim.x + threadIdx.x;
    if (k >= n) return;
    const int W = __ldg(wp);
    const int H = __ldg(hp);
    const float pk = ps[k];
    const int pos = pk > 0.0f;
    const int idx = ((bs[k] * 2 + pos) * H + ys[k]) * W + xs[k];
    atomicAdd(out + idx, fabsf(pk) * INV_STD_C);
}

// ---------------------------------------------------------------------------
// Clip: read float4 (should now hit L2); store ONLY if a component exceeds
// 1.0 (rare) to avoid the redundant 59 MB write stream.
// ---------------------------------------------------------------------------
__global__ void __launch_bounds__(256)
hist_clip_kernel(float* __restrict__ out, int n)
{
    const int n4 = n >> 2;
    const int i = blockIdx.x * blockDim.x + threadIdx.x;

    if (i < n4) {
        float4* o4 = reinterpret_cast<float4*>(out);
        float4 v = o4[i];
        if (v.x > CLIP_MAX_C || v.y > CLIP_MAX_C ||
            v.z > CLIP_MAX_C || v.w > CLIP_MAX_C) {
            v.x = fminf(v.x, CLIP_MAX_C);
            v.y = fminf(v.y, CLIP_MAX_C);
            v.z = fminf(v.z, CLIP_MAX_C);
            v.w = fminf(v.w, CLIP_MAX_C);
            o4[i] = v;
        }
    } else if (i == n4) {
        for (int k = n4 * 4; k < n; ++k) {
            const float v = out[k];
            if (v > CLIP_MAX_C) out[k] = CLIP_MAX_C;
        }
    }
}

// ---------------------------------------------------------------------------
extern "C" void kernel_launch(void* const* d_in, const int* in_sizes, int n_in,
                              void* d_out, int out_size)
{
    const int*   xs = (const int*)  d_in[0];
    const int*   ys = (const int*)  d_in[1];
    const float* ps = (const float*)d_in[2];
    const int*   bs = (const int*)  d_in[3];
    const int*   wp = (const int*)  d_in[4];
    const int*   hp = (const int*)  d_in[5];

    float* out = (float*)d_out;
    const int n = in_sizes[0];

    // 1) zero via stores with evict_last -> image resident in L2 pre-scatter
    {
        const int n4 = out_size >> 2;
        const int total_threads = n4 + ((out_size & 3) ? 1 : 0);
        const int blocks = (total_threads + 255) / 256;
        hist_zero_kernel<<<blocks, 256>>>(out, out_size);
    }

    // 2) scatter-add: 8 events/thread, streaming input loads
    {
        const int n8 = n >> 3;
        if (n8 > 0) {
            const int blocks = (n8 + 255) / 256;
            hist_scatter_kernel<<<blocks, 256>>>(
                (const int4*)xs, (const int4*)ys, (const float4*)ps,
                (const int4*)bs, wp, hp, out, n8);
        }
        if (n & 7) {
            hist_scatter_tail_kernel<<<1, 32>>>(xs, ys, ps, bs, wp, hp,
                                                out, n & ~7, n);
        }
    }

    // 3) clip (conditional store)
    {
        const int n4 = out_size >> 2;
        const int total_threads = n4 + ((out_size & 3) ? 1 : 0);
        const int blocks = (total_threads + 255) / 256;
        hist_clip_kernel<<<blocks, 256>>>(out, out_size);
    }
}